// round 8
// baseline (speedup 1.0000x reference)
#include <cuda_runtime.h>
#include <cuda_bf16.h>

// RobustSum L1 IRLS (K=3): x(128,1024) @ W(1024,1024) -> z(128,1024), fp32.
//
// Per (b,o): c = z/D1; t_i = fma(x_i, W_io, -c); r_i = 1/(|t_i|+eps) [MUFU];
// q = sum r*t, sw = sum r;  c' = (q + c*sw)/max(sw,1e-12);  out = D1*c.
//
// R7 (resubmitted after infra failure): thread = 1 b x 2 o x 256 i (packed-o
// f32x2 accumulators; fma slots per output unchanged at 3). Block = 128 thr =
// 4 warps (warp = i-chunk of 256). Block covers 1 b x 64 o. Grid (16,128) =
// 2048 blocks = 8192 warps (~55/SM demanded); launch_bounds(128,12) caps regs
// at 42 -> 12 CTAs/SM = 75% occ. L1 wavefronts double vs R6 (~114k cyc) but
// stay under the MUFU.RCP floor (170k cyc ~ 90us), which is the target.

#define DIN     1024
#define DOUT    1024
#define KITER   3
#define EPSILON 0.001f
#define ICHUNK  256
#define NTHREADS 128

typedef unsigned long long ull;

__device__ __forceinline__ ull pack2(float lo, float hi) {
    ull r; asm("mov.b64 %0, {%1,%2};" : "=l"(r) : "f"(lo), "f"(hi)); return r;
}
__device__ __forceinline__ void unpack2(ull v, float& lo, float& hi) {
    asm("mov.b64 {%0,%1}, %2;" : "=f"(lo), "=f"(hi) : "l"(v));
}
__device__ __forceinline__ ull fma2(ull a, ull b, ull c) {
    ull r; asm("fma.rn.f32x2 %0, %1, %2, %3;" : "=l"(r) : "l"(a), "l"(b), "l"(c)); return r;
}
__device__ __forceinline__ ull add2(ull a, ull b) {
    ull r; asm("add.rn.f32x2 %0, %1, %2;" : "=l"(r) : "l"(a), "l"(b)); return r;
}
__device__ __forceinline__ float rcpf(float a) {
    float r; asm("rcp.approx.f32 %0, %1;" : "=f"(r) : "f"(a)); return r;
}

__global__ __launch_bounds__(NTHREADS, 12)
void robust_sum_kernel(const float* __restrict__ x,
                       const float* __restrict__ w,
                       float* __restrict__ out)
{
    __shared__ float xs[DIN];                    // 4 KB: 1 b-row
    __shared__ ulonglong2 red[4][32];            // 2 KB: [iq][lane] = {q01, sw01}

    const int tid  = threadIdx.x;
    const int iq   = tid >> 5;                   // warp == i-chunk 0..3
    const int lane = tid & 31;
    const int o0   = blockIdx.x * 64 + lane * 2;
    const int b    = blockIdx.y;

    // Stage x row (1024 floats), coalesced float4: 128 thr x 2 each.
    {
        const float4* src = (const float4*)(x + (size_t)b * DIN);
        float4*       dst = (float4*)xs;
        #pragma unroll
        for (int t = tid; t < DIN / 4; t += NTHREADS)
            dst[t] = src[t];
    }
    __syncthreads();

    const float* xr    = &xs[iq * ICHUNK];
    const float* wbase = w + (size_t)(iq * ICHUNK) * DOUT + o0;

    // ---- pass 0: z = x @ W (as c = z/DIN) ----
    ull s01 = 0ULL;
    #pragma unroll 4
    for (int i = 0; i < ICHUNK; i++) {
        float xi = xr[i];
        ull wv = __ldg((const ull*)(wbase + (size_t)i * DOUT));
        s01 = fma2(pack2(xi, xi), wv, s01);
    }
    red[iq][lane] = make_ulonglong2(s01, 0ULL);
    __syncthreads();
    float c0, c1;
    {
        ull a = 0ULL;
        #pragma unroll
        for (int j = 0; j < 4; j++)
            a = add2(a, red[j][lane].x);
        float s0, s1;
        unpack2(a, s0, s1);
        c0 = s0 * (1.0f / DIN);
        c1 = s1 * (1.0f / DIN);
    }

    // ---- K IRLS iterations ----
    #pragma unroll 1
    for (int k = 0; k < KITER; k++) {
        const float n0 = -c0, n1 = -c1;
        ull q01 = 0ULL, sw01 = 0ULL;             // packed (o0,o1) accumulators
        #pragma unroll 4
        for (int i = 0; i < ICHUNK; i++) {
            float  xi = xr[i];
            float2 wv = __ldg((const float2*)(wbase + (size_t)i * DOUT));
            float t0 = fmaf(xi, wv.x, n0);       // xw - c
            float t1 = fmaf(xi, wv.y, n1);
            float r0 = rcpf(fabsf(t0) + EPSILON);
            float r1 = rcpf(fabsf(t1) + EPSILON);
            ull r01 = pack2(r0, r1);
            q01  = fma2(r01, pack2(t0, t1), q01);
            sw01 = add2(sw01, r01);
        }
        __syncthreads();                         // previous reduce reads done
        red[iq][lane] = make_ulonglong2(q01, sw01);
        __syncthreads();
        ull qa = 0ULL, wa = 0ULL;
        #pragma unroll
        for (int j = 0; j < 4; j++) {
            ulonglong2 v = red[j][lane];
            qa = add2(qa, v.x);
            wa = add2(wa, v.y);
        }
        float q0, q1, w0, w1;
        unpack2(qa, q0, q1);
        unpack2(wa, w0, w1);
        c0 = __fdividef(fmaf(c0, w0, q0), fmaxf(w0, 1e-12f));
        c1 = __fdividef(fmaf(c1, w1, q1), fmaxf(w1, 1e-12f));
    }

    if (iq == 0) {
        *(float2*)(out + (size_t)b * DOUT + o0) =
            make_float2((float)DIN * c0, (float)DIN * c1);
    }
}

extern "C" void kernel_launch(void* const* d_in, const int* in_sizes, int n_in,
                              void* d_out, int out_size)
{
    const float* x = (const float*)d_in[0];   // (128, 1024)
    const float* w = (const float*)d_in[1];   // (1024, 1024)
    float* out = (float*)d_out;               // (128, 1024)

    dim3 grid(DOUT / 64, 128);                // (16, 128) = 2048 blocks
    robust_sum_kernel<<<grid, NTHREADS>>>(x, w, out);
}